// round 15
// baseline (speedup 1.0000x reference)
#include <cuda_runtime.h>
#include <cstdint>
#include <cstddef>

#define NNODES 10000
#define NEDGES 320000
#define FDIM   128
#define NTILES 79            // ceil(10000/128)

// ---------------- device scratch (allocation-free rule: __device__ globals) ---
__device__ float g_B1[NNODES * FDIM];   // h1 / s1out
__device__ float g_B2[NNODES * FDIM];   // h2
__device__ float g_B3[NNODES * FDIM];   // a1out (a-branch private)
__device__ float g_AGG[NNODES * FDIM];  // s-branch agg buffer
__device__ float g_AGG2[NNODES * FDIM]; // a-branch agg buffer
__device__ float g_inv[NNODES];
__device__ int   g_deg[NNODES];
__device__ int   g_cur[NNODES];
__device__ int   g_ptr[NNODES + 1];
__device__ int   g_csrc[NEDGES];
// pre-shuffled tf32 operands for the final GEMM: [tile][chunk][4096] u32
// zero-initialized BSS; padding slots are only ever written zero -> stay zero.
__device__ uint32_t g_Ashuf[NTILES * 8 * 4096];   // ~10.3 MB
__device__ uint32_t g_Bshuf[NTILES * 8 * 4096];   // ~10.3 MB

// ---------------- CSR construction -------------------------------------------
__global__ void zero_kernel() {
    int i = blockIdx.x * blockDim.x + threadIdx.x;
    if (i < NNODES) { g_deg[i] = 0; g_cur[i] = 0; }
}

__global__ void count_kernel(const int* __restrict__ dst) {
    int e = blockIdx.x * blockDim.x + threadIdx.x;
    if (e < NEDGES) atomicAdd(&g_deg[dst[e]], 1);
}

// single-block scan: 1024 thr x 10 elems, shfl warp scans (R12 version)
__global__ void __launch_bounds__(1024) scan_kernel() {
    __shared__ int wtot[32];
    const int tid  = threadIdx.x;
    const int lane = tid & 31, wid = tid >> 5;
    const int base = tid * 10;
    int v[10], loc[10];
    int tot = 0;
#pragma unroll
    for (int i = 0; i < 10; i++) {
        v[i] = (base + i < NNODES) ? g_deg[base + i] : 0;
        loc[i] = tot;
        tot += v[i];
    }
    int inc = tot;
#pragma unroll
    for (int off = 1; off < 32; off <<= 1) {
        int t = __shfl_up_sync(0xffffffffu, inc, off);
        if (lane >= off) inc += t;
    }
    if (lane == 31) wtot[wid] = inc;
    __syncthreads();
    if (wid == 0) {
        int w = wtot[lane];
#pragma unroll
        for (int off = 1; off < 32; off <<= 1) {
            int t = __shfl_up_sync(0xffffffffu, w, off);
            if (lane >= off) w += t;
        }
        wtot[lane] = w;
    }
    __syncthreads();
    const int offset = inc - tot + (wid > 0 ? wtot[wid - 1] : 0);  // exclusive
#pragma unroll
    for (int i = 0; i < 10; i++) {
        const int idx = base + i;
        if (idx < NNODES) {
            g_ptr[idx] = offset + loc[i];
            g_inv[idx] = 1.0f / fmaxf((float)v[i], 1.0f);
        }
    }
    if (tid == 1023) g_ptr[NNODES] = offset + tot;
}

__global__ void fill_kernel(const int* __restrict__ src, const int* __restrict__ dst) {
    int e = blockIdx.x * blockDim.x + threadIdx.x;
    if (e < NEDGES) {
        int d = dst[e];
        int pos = g_ptr[d] + atomicAdd(&g_cur[d], 1);
        g_csrc[pos] = src[e];
    }
}

// ---------------- mean aggregation: one WARP per node, 4-way (R12) ------------
__global__ void agg_kernel(const float* __restrict__ X, float* __restrict__ O) {
    const int gw   = (blockIdx.x * blockDim.x + threadIdx.x) >> 5;  // node
    const int lane = threadIdx.x & 31;
    if (gw >= NNODES) return;
    const float4* __restrict__ Xv = (const float4*)X;
    const int beg = g_ptr[gw], end = g_ptr[gw + 1];
    float4 a0 = make_float4(0.f, 0.f, 0.f, 0.f);
    float4 a1 = make_float4(0.f, 0.f, 0.f, 0.f);
    float4 a2 = make_float4(0.f, 0.f, 0.f, 0.f);
    float4 a3 = make_float4(0.f, 0.f, 0.f, 0.f);
    int e = beg;
    for (; e + 4 <= end; e += 4) {
        const int i0 = g_csrc[e], i1 = g_csrc[e + 1];
        const int i2 = g_csrc[e + 2], i3 = g_csrc[e + 3];
        const float4 v0 = Xv[i0 * 32 + lane];
        const float4 v1 = Xv[i1 * 32 + lane];
        const float4 v2 = Xv[i2 * 32 + lane];
        const float4 v3 = Xv[i3 * 32 + lane];
        a0.x += v0.x; a0.y += v0.y; a0.z += v0.z; a0.w += v0.w;
        a1.x += v1.x; a1.y += v1.y; a1.z += v1.z; a1.w += v1.w;
        a2.x += v2.x; a2.y += v2.y; a2.z += v2.z; a2.w += v2.w;
        a3.x += v3.x; a3.y += v3.y; a3.z += v3.z; a3.w += v3.w;
    }
    for (; e < end; e++) {
        const float4 v = Xv[g_csrc[e] * 32 + lane];
        a0.x += v.x; a0.y += v.y; a0.z += v.z; a0.w += v.w;
    }
    const float inv = g_inv[gw];
    float4 o;
    o.x = (a0.x + a1.x + a2.x + a3.x) * inv;
    o.y = (a0.y + a1.y + a2.y + a3.y) * inv;
    o.z = (a0.z + a1.z + a2.z + a3.z) * inv;
    o.w = (a0.w + a1.w + a2.w + a3.w) * inv;
    ((float4*)O)[gw * 32 + lane] = o;
}
#define AGG_GRID ((NNODES * 32 + 255) / 256)

__device__ __forceinline__ uint32_t f2tf32(float v) {
    uint32_t t;
    asm("cvt.rna.tf32.f32 %0, %1;" : "=r"(t) : "f"(v));
    return t;
}

// ---- fused: final aggregation -> shuffled B chunks 0-3 directly --------------
__global__ void agg_shuf_kernel(const float* __restrict__ X) {
    const int gw   = (blockIdx.x * blockDim.x + threadIdx.x) >> 5;  // node j
    const int lane = threadIdx.x & 31;
    if (gw >= NNODES) return;
    const float4* __restrict__ Xv = (const float4*)X;
    const int beg = g_ptr[gw], end = g_ptr[gw + 1];
    float4 a0 = make_float4(0.f, 0.f, 0.f, 0.f);
    float4 a1 = make_float4(0.f, 0.f, 0.f, 0.f);
    float4 a2 = make_float4(0.f, 0.f, 0.f, 0.f);
    float4 a3 = make_float4(0.f, 0.f, 0.f, 0.f);
    int e = beg;
    for (; e + 4 <= end; e += 4) {
        const int i0 = g_csrc[e], i1 = g_csrc[e + 1];
        const int i2 = g_csrc[e + 2], i3 = g_csrc[e + 3];
        const float4 v0 = Xv[i0 * 32 + lane];
        const float4 v1 = Xv[i1 * 32 + lane];
        const float4 v2 = Xv[i2 * 32 + lane];
        const float4 v3 = Xv[i3 * 32 + lane];
        a0.x += v0.x; a0.y += v0.y; a0.z += v0.z; a0.w += v0.w;
        a1.x += v1.x; a1.y += v1.y; a1.z += v1.z; a1.w += v1.w;
        a2.x += v2.x; a2.y += v2.y; a2.z += v2.z; a2.w += v2.w;
        a3.x += v3.x; a3.y += v3.y; a3.z += v3.z; a3.w += v3.w;
    }
    for (; e < end; e++) {
        const float4 v = Xv[g_csrc[e] * 32 + lane];
        a0.x += v.x; a0.y += v.y; a0.z += v.z; a0.w += v.w;
    }
    const float inv = g_inv[gw];
    float ov[4];
    ov[0] = (a0.x + a1.x + a2.x + a3.x) * inv;
    ov[1] = (a0.y + a1.y + a2.y + a3.y) * inv;
    ov[2] = (a0.z + a1.z + a2.z + a3.z) * inv;
    ov[3] = (a0.w + a1.w + a2.w + a3.w) * inv;
    const int tile  = gw >> 7;
    const int jloc  = gw & 127;
    const int nt    = jloc >> 3;
    const int g     = jloc & 7;
    const int chunk = lane >> 3;
    uint32_t* dst = g_Bshuf + (size_t)(tile * 8 + chunk) * 4096;
#pragma unroll
    for (int e2 = 0; e2 < 4; e2++) {
        const int k  = 4 * lane + e2;
        const int kl2 = k & 31;
        const int kt = kl2 >> 3;
        const int kl = kl2 & 7;
        const int lw = ((g << 2) | (kl & 3)) ^ (kt << 3);
        const int r  = kl >> 2;
        dst[((kt * 16 + nt) * 32 + lw) * 2 + r] = f2tf32(ov[e2]);
    }
}

// ---------------- fused SAGE layer (SIMT): Y = relu(AGG@Wl + X@Wr + b) -------
__global__ void __launch_bounds__(256)
layer_kernel(const float* __restrict__ A0,
             const float* __restrict__ A1,
             const float* __restrict__ W0,
             const float* __restrict__ W1,
             const float* __restrict__ bias,
             float* __restrict__ Y) {
    __shared__ float As[8][64];
    __shared__ float Bs[8][128];
    int tid = threadIdx.x;
    int r0 = blockIdx.x * 64;

    float acc[4][8];
#pragma unroll
    for (int i = 0; i < 4; i++)
#pragma unroll
        for (int j = 0; j < 8; j++) acc[i][j] = 0.f;

    int rowb = (tid >> 4) * 4;      // 0..60
    int colb = (tid & 15) * 8;      // 0..120

    for (int phase = 0; phase < 2; phase++) {
        const float* A = phase ? A1 : A0;
        const float* W = phase ? W1 : W0;
        for (int k0 = 0; k0 < 128; k0 += 8) {
            if (tid < 128) {        // A tile: 64 rows x 8 k, transposed
                int lrow = tid >> 1;
                int lc   = (tid & 1) * 4;
                float4 av = make_float4(0.f, 0.f, 0.f, 0.f);
                int grow = r0 + lrow;
                if (grow < NNODES) av = *(const float4*)&A[grow * FDIM + k0 + lc];
                As[lc + 0][lrow] = av.x;
                As[lc + 1][lrow] = av.y;
                As[lc + 2][lrow] = av.z;
                As[lc + 3][lrow] = av.w;
            }
            {                        // B tile: 8 k x 128 cols, one float4/thread
                int kk = tid >> 5, j4 = (tid & 31) * 4;
                *(float4*)&Bs[kk][j4] = *(const float4*)&W[(k0 + kk) * 128 + j4];
            }
            __syncthreads();
#pragma unroll
            for (int k = 0; k < 8; k++) {
                float a[4], b[8];
                *(float4*)&a[0] = *(const float4*)&As[k][rowb];
                *(float4*)&b[0] = *(const float4*)&Bs[k][colb];
                *(float4*)&b[4] = *(const float4*)&Bs[k][colb + 4];
#pragma unroll
                for (int ii = 0; ii < 4; ii++)
#pragma unroll
                    for (int jj = 0; jj < 8; jj++) acc[ii][jj] += a[ii] * b[jj];
            }
            __syncthreads();
        }
    }
#pragma unroll
    for (int ii = 0; ii < 4; ii++) {
        int grow = r0 + rowb + ii;
        if (grow < NNODES) {
#pragma unroll
            for (int jj = 0; jj < 8; jj += 4) {
                float4 o;
                o.x = fmaxf(acc[ii][jj + 0] + bias[colb + jj + 0], 0.f);
                o.y = fmaxf(acc[ii][jj + 1] + bias[colb + jj + 1], 0.f);
                o.z = fmaxf(acc[ii][jj + 2] + bias[colb + jj + 2], 0.f);
                o.w = fmaxf(acc[ii][jj + 3] + bias[colb + jj + 3], 0.f);
                *(float4*)&Y[(size_t)grow * 128 + colb + jj] = o;
            }
        }
    }
}
#define LAYER_GRID ((NNODES + 63) / 64)

// ================== tf32 mma.sync final GEMM (sm_80+ path) ===================
__device__ __forceinline__ void mma_tf32(float* c, const uint32_t* a, const uint32_t* b) {
    asm volatile(
        "mma.sync.aligned.m16n8k8.row.col.f32.tf32.tf32.f32 "
        "{%0,%1,%2,%3}, {%4,%5,%6,%7}, {%8,%9}, {%0,%1,%2,%3};\n"
        : "+f"(c[0]), "+f"(c[1]), "+f"(c[2]), "+f"(c[3])
        : "r"(a[0]), "r"(a[1]), "r"(a[2]), "r"(a[3]),
          "r"(b[0]), "r"(b[1]));
}

__device__ __forceinline__ void cp16(uint32_t smem_addr, const void* gptr) {
    asm volatile("cp.async.cg.shared.global [%0], [%1], 16;"
                 :: "r"(smem_addr), "l"(gptr));
}

// ---- pre-shuffle A: weights W[k, i] -> fragment blocks ----------------------
__global__ void shufA_kernel(const float* __restrict__ Wl,
                             const float* __restrict__ Wr) {
    const int tile  = blockIdx.x;
    const int chunk = blockIdx.y;
    const int phase = chunk >> 2;
    const int kc    = (chunk & 3) * 32;
    const float* __restrict__ W = phase ? Wr : Wl;
    const int ib   = tile * 128;
    const int warp = threadIdx.x >> 5;
    const int lane = threadIdx.x & 31;
    const int kt   = lane >> 3;
    const int t4v  = lane & 3;
    const int khi  = (lane >> 2) & 1;
    const float* Wp = W + (size_t)(kc + lane) * NNODES + ib;
    uint32_t* dst = g_Ashuf + (size_t)(tile * 8 + chunk) * 4096;
#pragma unroll
    for (int mm = 0; mm < 16; mm++) {
        const int m = warp * 16 + mm;
        float v = 0.f;
        if (ib + m < NNODES) v = Wp[m];
        const int g  = m & 7;
        const int hi = (m >> 3) & 1;
        const int lw = ((g << 2) | t4v) ^ (kt << 3);
        const int r  = (khi << 1) | hi;
        dst[((kt * 8 + warp) * 32 + lw) * 4 + r] = f2tf32(v);
    }
}

// ---- pre-shuffle B for S1 (chunks 4..7 only) --------------------------------
__global__ void shufB_s1_kernel(const float* __restrict__ S1) {
    const int tile  = blockIdx.x;
    const int chunk = blockIdx.y + 4;
    const int kc    = blockIdx.y * 32;
    const int jb   = tile * 128;
    const int tid  = threadIdx.x;
    const int j    = tid >> 1;
    const int half = tid & 1;
    const int nt   = j >> 3;
    const int g    = j & 7;
    const bool jv  = (jb + j) < NNODES;
    const float* Fp = S1 + (size_t)(jb + j) * FDIM + kc + half * 16;
    uint32_t* dst = g_Bshuf + (size_t)(tile * 8 + chunk) * 4096;
#pragma unroll
    for (int q = 0; q < 4; q++) {
        float4 v4 = make_float4(0.f, 0.f, 0.f, 0.f);
        if (jv) v4 = *(const float4*)(Fp + q * 4);
        float vv[4] = {v4.x, v4.y, v4.z, v4.w};
#pragma unroll
        for (int e = 0; e < 4; e++) {
            const int k  = half * 16 + q * 4 + e;
            const int kt = k >> 3;
            const int kl = k & 7;
            const int lw = ((g << 2) | (kl & 3)) ^ (kt << 3);
            const int r  = kl >> 2;
            dst[((kt * 16 + nt) * 32 + lw) * 2 + r] = f2tf32(vv[e]);
        }
    }
}

// ---- final GEMM: B via cp.async double-buffered smem, A register-direct ------
// A fragments load straight from pre-shuffled gmem (L1/L2-resident; coalesced
// 512B spans per warp), double-buffered one kt ahead. SMEM holds only B.
extern __shared__ uint32_t dynsmem[];   // [2][4096] B = 32KB

__global__ void __launch_bounds__(128, 2)
final_tc_kernel(const float* __restrict__ bias,  // [NNODES]
                float* __restrict__ OUT) {       // [NNODES, NNODES]
    uint32_t* sB = dynsmem;

    const int tid  = threadIdx.x;
    const int lane = tid & 31;
    const int warp = tid >> 5;
    const int wm   = warp >> 1;
    const int wn   = warp & 1;
    const int ib   = blockIdx.y * 128;
    const int jb   = blockIdx.x * 128;

    const uint32_t* __restrict__ srcA = g_Ashuf + (size_t)blockIdx.y * 8 * 4096;
    const uint32_t* __restrict__ srcB = g_Bshuf + (size_t)blockIdx.x * 8 * 4096;

    float acc[4][8][4];
#pragma unroll
    for (int mi = 0; mi < 4; mi++)
#pragma unroll
        for (int ni = 0; ni < 8; ni++)
#pragma unroll
            for (int r = 0; r < 4; r++) acc[mi][ni][r] = 0.f;

    const uint32_t sB_u = (uint32_t)__cvta_generic_to_shared(sB);

    auto issueB = [&](int chunk) {
        const int buf = chunk & 1;
        const uint32_t* b = srcB + chunk * 4096;
        const uint32_t sb = sB_u + buf * 4096 * 4;
#pragma unroll
        for (int it = 0; it < 8; it++) {
            const int off = (tid + it * 128) * 4;
            cp16(sb + off * 4, b + off);
        }
        asm volatile("cp.async.commit_group;");
    };

    // register-direct A fragment load for (chunk, kt)
    auto ldA = [&](int chunk, int kt, uint32_t af[4][4]) {
        const uint4* __restrict__ a = (const uint4*)(srcA + chunk * 4096);
        const int lx = lane ^ (kt << 3);
#pragma unroll
        for (int mi = 0; mi < 4; mi++) {
            const uint4 v = __ldg(&a[(kt * 8 + wm * 4 + mi) * 32 + lx]);
            af[mi][0] = v.x; af[mi][1] = v.y; af[mi][2] = v.z; af[mi][3] = v.w;
        }
    };

    uint32_t afb[2][4][4];
    issueB(0);
    ldA(0, 0, afb[0]);
    int cur = 0;

    for (int c = 0; c < 8; c++) {
        if (c < 7) {
            issueB(c + 1);
            asm volatile("cp.async.wait_group 1;");
        } else {
            asm volatile("cp.async.wait_group 0;");
        }
        __syncthreads();

        const uint32_t* cB = sB + (c & 1) * 4096;
#pragma unroll
        for (int kt = 0; kt < 4; kt++) {
            // prefetch next kt's A fragments (crosses chunk boundary at kt=3)
            const int nc  = (kt == 3) ? c + 1 : c;
            const int nkt = (kt + 1) & 3;
            if (nc < 8) ldA(nc, nkt, afb[cur ^ 1]);

            const int lx = lane ^ (kt << 3);
            uint32_t bf[8][2];
#pragma unroll
            for (int ni = 0; ni < 8; ni++) {
                const uint2 v = *(const uint2*)&cB[((kt * 16 + wn * 8 + ni) * 32 + lx) * 2];
                bf[ni][0] = v.x; bf[ni][1] = v.y;
            }
#pragma unroll
            for (int mi = 0; mi < 4; mi++)
#pragma unroll
                for (int ni = 0; ni < 8; ni++)
                    mma_tf32(acc[mi][ni], afb[cur][mi], bf[ni]);
            cur ^= 1;
        }
        __syncthreads();
    }

    const int g  = lane >> 2;
    const int t4 = lane & 3;
#pragma unroll
    for (int mi = 0; mi < 4; mi++) {
        const int i0 = ib + (wm * 4 + mi) * 16 + g;
        const int i1 = i0 + 8;
        const float bv0 = (i0 < NNODES) ? bias[i0] : 0.f;
        const float bv1 = (i1 < NNODES) ? bias[i1] : 0.f;
#pragma unroll
        for (int ni = 0; ni < 8; ni++) {
            const int j = jb + (wn * 8 + ni) * 8 + t4 * 2;
            if (j < NNODES) {
                if (i0 < NNODES) {
                    float2 o;
                    o.x = fmaxf(acc[mi][ni][0] + bv0, 0.f);
                    o.y = fmaxf(acc[mi][ni][1] + bv0, 0.f);
                    *(float2*)&OUT[(size_t)i0 * NNODES + j] = o;
                }
                if (i1 < NNODES) {
                    float2 o;
                    o.x = fmaxf(acc[mi][ni][2] + bv1, 0.f);
                    o.y = fmaxf(acc[mi][ni][3] + bv1, 0.f);
                    *(float2*)&OUT[(size_t)i1 * NNODES + j] = o;
                }
            }
        }
    }
}

// ---------------- launch ------------------------------------------------------
extern "C" void kernel_launch(void* const* d_in, const int* in_sizes, int n_in,
                              void* d_out, int out_size) {
    const float* x   = (const float*)d_in[0];
    const int*   ei  = (const int*)d_in[1];
    const int*   src = ei;
    const int*   dst = ei + NEDGES;
    const float *Wl_e1 = (const float*)d_in[2],  *bl_e1 = (const float*)d_in[3],  *Wr_e1 = (const float*)d_in[4];
    const float *Wl_e2 = (const float*)d_in[5],  *bl_e2 = (const float*)d_in[6],  *Wr_e2 = (const float*)d_in[7];
    const float *Wl_a1 = (const float*)d_in[8],  *bl_a1 = (const float*)d_in[9],  *Wr_a1 = (const float*)d_in[10];
    const float *Wl_a2 = (const float*)d_in[11], *bl_a2 = (const float*)d_in[12], *Wr_a2 = (const float*)d_in[13];
    const float *Wl_s1 = (const float*)d_in[14], *bl_s1 = (const float*)d_in[15], *Wr_s1 = (const float*)d_in[16];
    const float *Wl_s2 = (const float*)d_in[17], *bl_s2 = (const float*)d_in[18], *Wr_s2 = (const float*)d_in[19];

    float* out    = (float*)d_out;
    float* xh_out = out + (size_t)NNODES * NNODES;

    float *pB1, *pB2, *pB3, *pAGG, *pAGG2;
    cudaGetSymbolAddress((void**)&pB1,   g_B1);
    cudaGetSymbolAddress((void**)&pB2,   g_B2);
    cudaGetSymbolAddress((void**)&pB3,   g_B3);
    cudaGetSymbolAddress((void**)&pAGG,  g_AGG);
    cudaGetSymbolAddress((void**)&pAGG2, g_AGG2);

    static cudaStream_t s_a = nullptr;
    static cudaEvent_t ev0 = nullptr, ev_shufA = nullptr, ev_fork = nullptr, ev_join = nullptr;
    if (!s_a) {
        cudaStreamCreateWithFlags(&s_a, cudaStreamNonBlocking);
        cudaEventCreateWithFlags(&ev0,      cudaEventDisableTiming);
        cudaEventCreateWithFlags(&ev_shufA, cudaEventDisableTiming);
        cudaEventCreateWithFlags(&ev_fork,  cudaEventDisableTiming);
        cudaEventCreateWithFlags(&ev_join,  cudaEventDisableTiming);
        cudaFuncSetAttribute(final_tc_kernel,
                             cudaFuncAttributeMaxDynamicSharedMemorySize, 32768);
    }

    dim3 fg((NNODES + 127) / 128, (NNODES + 127) / 128);  // 79x79
    dim3 sgA(NTILES, 8);
    dim3 sgB(NTILES, 4);

    // fork side stream at t=0: shufA runs concurrently with CSR build
    cudaEventRecord(ev0, 0);
    cudaStreamWaitEvent(s_a, ev0, 0);
    shufA_kernel<<<sgA, 256, 0, s_a>>>(Wl_s2, Wr_s2);
    cudaEventRecord(ev_shufA, s_a);

    // CSR build (main)
    zero_kernel<<<(NNODES + 255) / 256, 256>>>();
    count_kernel<<<(NEDGES + 255) / 256, 256>>>(dst);
    scan_kernel<<<1, 1024>>>();
    fill_kernel<<<(NEDGES + 255) / 256, 256>>>(src, dst);

    // encoder (shared prefix)
    agg_kernel<<<AGG_GRID, 256>>>(x, pAGG);
    layer_kernel<<<LAYER_GRID, 256>>>(pAGG, x, Wl_e1, Wr_e1, bl_e1, pB1);       // h1
    agg_kernel<<<AGG_GRID, 256>>>(pB1, pAGG);
    layer_kernel<<<LAYER_GRID, 256>>>(pAGG, pB1, Wl_e2, Wr_e2, bl_e2, pB2);     // h2

    // fork: attribute decoder on side stream
    cudaEventRecord(ev_fork, 0);
    cudaStreamWaitEvent(s_a, ev_fork, 0);
    agg_kernel<<<AGG_GRID, 256, 0, s_a>>>(pB2, pAGG2);
    layer_kernel<<<LAYER_GRID, 256, 0, s_a>>>(pAGG2, pB2, Wl_a1, Wr_a1, bl_a1, pB3);   // a1
    agg_kernel<<<AGG_GRID, 256, 0, s_a>>>(pB3, pAGG2);
    layer_kernel<<<LAYER_GRID, 256, 0, s_a>>>(pAGG2, pB3, Wl_a2, Wr_a2, bl_a2, xh_out);// xh
    cudaEventRecord(ev_join, s_a);

    // structure decoder + final GEMM on main stream
    agg_kernel<<<AGG_GRID, 256>>>(pB2, pAGG);
    layer_kernel<<<LAYER_GRID, 256>>>(pAGG, pB2, Wl_s1, Wr_s1, bl_s1, pB1);     // s1
    shufB_s1_kernel<<<sgB, 256>>>(pB1);                                 // B chunks 4-7
    agg_shuf_kernel<<<AGG_GRID, 256>>>(pB1);                            // B chunks 0-3
    cudaStreamWaitEvent(0, ev_shufA, 0);
    final_tc_kernel<<<fg, 128, 32768>>>(bl_s2, out);                    // s

    cudaStreamWaitEvent(0, ev_join, 0);
}

// round 16
// speedup vs baseline: 1.0232x; 1.0232x over previous
#include <cuda_runtime.h>
#include <cstdint>
#include <cstddef>

#define NNODES 10000
#define NEDGES 320000
#define FDIM   128
#define NTILES 79            // ceil(10000/128)

// ---------------- device scratch (allocation-free rule: __device__ globals) ---
__device__ float g_B1[NNODES * FDIM];   // h1 / s1out
__device__ float g_B2[NNODES * FDIM];   // h2
__device__ float g_B3[NNODES * FDIM];   // a1out (a-branch private)
__device__ float g_AGG[NNODES * FDIM];  // s-branch agg buffer
__device__ float g_AGG2[NNODES * FDIM]; // a-branch agg buffer
__device__ float g_inv[NNODES];
__device__ int   g_deg[NNODES];
__device__ int   g_cur[NNODES];
__device__ int   g_ptr[NNODES + 1];
__device__ int   g_csrc[NEDGES];
// pre-shuffled tf32 operands for the final GEMM: [tile][chunk][4096] u32
// zero-initialized BSS; padding slots are only ever written zero -> stay zero.
__device__ uint32_t g_Ashuf[NTILES * 8 * 4096];   // ~10.3 MB
__device__ uint32_t g_Bshuf[NTILES * 8 * 4096];   // ~10.3 MB

// ---------------- CSR construction -------------------------------------------
__global__ void zero_kernel() {
    int i = blockIdx.x * blockDim.x + threadIdx.x;
    if (i < NNODES) { g_deg[i] = 0; g_cur[i] = 0; }
}

__global__ void count_kernel(const int* __restrict__ dst) {
    int e = blockIdx.x * blockDim.x + threadIdx.x;
    if (e < NEDGES) atomicAdd(&g_deg[dst[e]], 1);
}

// single-block scan: 1024 thr x 10 elems, shfl warp scans (R12 version)
__global__ void __launch_bounds__(1024) scan_kernel() {
    __shared__ int wtot[32];
    const int tid  = threadIdx.x;
    const int lane = tid & 31, wid = tid >> 5;
    const int base = tid * 10;
    int v[10], loc[10];
    int tot = 0;
#pragma unroll
    for (int i = 0; i < 10; i++) {
        v[i] = (base + i < NNODES) ? g_deg[base + i] : 0;
        loc[i] = tot;
        tot += v[i];
    }
    int inc = tot;
#pragma unroll
    for (int off = 1; off < 32; off <<= 1) {
        int t = __shfl_up_sync(0xffffffffu, inc, off);
        if (lane >= off) inc += t;
    }
    if (lane == 31) wtot[wid] = inc;
    __syncthreads();
    if (wid == 0) {
        int w = wtot[lane];
#pragma unroll
        for (int off = 1; off < 32; off <<= 1) {
            int t = __shfl_up_sync(0xffffffffu, w, off);
            if (lane >= off) w += t;
        }
        wtot[lane] = w;
    }
    __syncthreads();
    const int offset = inc - tot + (wid > 0 ? wtot[wid - 1] : 0);  // exclusive
#pragma unroll
    for (int i = 0; i < 10; i++) {
        const int idx = base + i;
        if (idx < NNODES) {
            g_ptr[idx] = offset + loc[i];
            g_inv[idx] = 1.0f / fmaxf((float)v[i], 1.0f);
        }
    }
    if (tid == 1023) g_ptr[NNODES] = offset + tot;
}

__global__ void fill_kernel(const int* __restrict__ src, const int* __restrict__ dst) {
    int e = blockIdx.x * blockDim.x + threadIdx.x;
    if (e < NEDGES) {
        int d = dst[e];
        int pos = g_ptr[d] + atomicAdd(&g_cur[d], 1);
        g_csrc[pos] = src[e];
    }
}

// ---------------- mean aggregation: one WARP per node, 4-way (R12) ------------
__global__ void agg_kernel(const float* __restrict__ X, float* __restrict__ O) {
    const int gw   = (blockIdx.x * blockDim.x + threadIdx.x) >> 5;  // node
    const int lane = threadIdx.x & 31;
    if (gw >= NNODES) return;
    const float4* __restrict__ Xv = (const float4*)X;
    const int beg = g_ptr[gw], end = g_ptr[gw + 1];
    float4 a0 = make_float4(0.f, 0.f, 0.f, 0.f);
    float4 a1 = make_float4(0.f, 0.f, 0.f, 0.f);
    float4 a2 = make_float4(0.f, 0.f, 0.f, 0.f);
    float4 a3 = make_float4(0.f, 0.f, 0.f, 0.f);
    int e = beg;
    for (; e + 4 <= end; e += 4) {
        const int i0 = g_csrc[e], i1 = g_csrc[e + 1];
        const int i2 = g_csrc[e + 2], i3 = g_csrc[e + 3];
        const float4 v0 = Xv[i0 * 32 + lane];
        const float4 v1 = Xv[i1 * 32 + lane];
        const float4 v2 = Xv[i2 * 32 + lane];
        const float4 v3 = Xv[i3 * 32 + lane];
        a0.x += v0.x; a0.y += v0.y; a0.z += v0.z; a0.w += v0.w;
        a1.x += v1.x; a1.y += v1.y; a1.z += v1.z; a1.w += v1.w;
        a2.x += v2.x; a2.y += v2.y; a2.z += v2.z; a2.w += v2.w;
        a3.x += v3.x; a3.y += v3.y; a3.z += v3.z; a3.w += v3.w;
    }
    for (; e < end; e++) {
        const float4 v = Xv[g_csrc[e] * 32 + lane];
        a0.x += v.x; a0.y += v.y; a0.z += v.z; a0.w += v.w;
    }
    const float inv = g_inv[gw];
    float4 o;
    o.x = (a0.x + a1.x + a2.x + a3.x) * inv;
    o.y = (a0.y + a1.y + a2.y + a3.y) * inv;
    o.z = (a0.z + a1.z + a2.z + a3.z) * inv;
    o.w = (a0.w + a1.w + a2.w + a3.w) * inv;
    ((float4*)O)[gw * 32 + lane] = o;
}
#define AGG_GRID ((NNODES * 32 + 255) / 256)

__device__ __forceinline__ uint32_t f2tf32(float v) {
    uint32_t t;
    asm("cvt.rna.tf32.f32 %0, %1;" : "=r"(t) : "f"(v));
    return t;
}

// ---- fused: final aggregation -> shuffled B chunks 0-3, AND own-row S1
//      values -> shuffled B chunks 4-7 (replaces the separate shufB pass) -----
__global__ void agg_shuf_kernel(const float* __restrict__ X) {  // X = S1
    const int gw   = (blockIdx.x * blockDim.x + threadIdx.x) >> 5;  // node j
    const int lane = threadIdx.x & 31;
    if (gw >= NNODES) return;
    const float4* __restrict__ Xv = (const float4*)X;
    const int beg = g_ptr[gw], end = g_ptr[gw + 1];
    float4 a0 = make_float4(0.f, 0.f, 0.f, 0.f);
    float4 a1 = make_float4(0.f, 0.f, 0.f, 0.f);
    float4 a2 = make_float4(0.f, 0.f, 0.f, 0.f);
    float4 a3 = make_float4(0.f, 0.f, 0.f, 0.f);
    int e = beg;
    for (; e + 4 <= end; e += 4) {
        const int i0 = g_csrc[e], i1 = g_csrc[e + 1];
        const int i2 = g_csrc[e + 2], i3 = g_csrc[e + 3];
        const float4 v0 = Xv[i0 * 32 + lane];
        const float4 v1 = Xv[i1 * 32 + lane];
        const float4 v2 = Xv[i2 * 32 + lane];
        const float4 v3 = Xv[i3 * 32 + lane];
        a0.x += v0.x; a0.y += v0.y; a0.z += v0.z; a0.w += v0.w;
        a1.x += v1.x; a1.y += v1.y; a1.z += v1.z; a1.w += v1.w;
        a2.x += v2.x; a2.y += v2.y; a2.z += v2.z; a2.w += v2.w;
        a3.x += v3.x; a3.y += v3.y; a3.z += v3.z; a3.w += v3.w;
    }
    for (; e < end; e++) {
        const float4 v = Xv[g_csrc[e] * 32 + lane];
        a0.x += v.x; a0.y += v.y; a0.z += v.z; a0.w += v.w;
    }
    const float inv = g_inv[gw];
    float ov[4];
    ov[0] = (a0.x + a1.x + a2.x + a3.x) * inv;
    ov[1] = (a0.y + a1.y + a2.y + a3.y) * inv;
    ov[2] = (a0.z + a1.z + a2.z + a3.z) * inv;
    ov[3] = (a0.w + a1.w + a2.w + a3.w) * inv;

    // own-row S1 values for the second K-phase (chunks 4..7)
    const float4 own = Xv[gw * 32 + lane];
    float sv[4] = {own.x, own.y, own.z, own.w};

    const int tile  = gw >> 7;
    const int jloc  = gw & 127;
    const int nt    = jloc >> 3;
    const int g     = jloc & 7;
    const int chunk = lane >> 3;                    // k = 4*lane+e2, chunk = k>>5
    uint32_t* dst0 = g_Bshuf + (size_t)(tile * 8 + chunk) * 4096;      // AGG phase
    uint32_t* dst1 = g_Bshuf + (size_t)(tile * 8 + 4 + chunk) * 4096;  // S1 phase
#pragma unroll
    for (int e2 = 0; e2 < 4; e2++) {
        const int k   = 4 * lane + e2;
        const int kl2 = k & 31;
        const int kt  = kl2 >> 3;
        const int kl  = kl2 & 7;
        const int lw  = ((g << 2) | (kl & 3)) ^ (kt << 3);
        const int r   = kl >> 2;
        const int slot = ((kt * 16 + nt) * 32 + lw) * 2 + r;
        dst0[slot] = f2tf32(ov[e2]);
        dst1[slot] = f2tf32(sv[e2]);
    }
}

// ---------------- fused SAGE layer (SIMT): Y = relu(AGG@Wl + X@Wr + b) -------
__global__ void __launch_bounds__(256)
layer_kernel(const float* __restrict__ A0,
             const float* __restrict__ A1,
             const float* __restrict__ W0,
             const float* __restrict__ W1,
             const float* __restrict__ bias,
             float* __restrict__ Y) {
    __shared__ float As[8][64];
    __shared__ float Bs[8][128];
    int tid = threadIdx.x;
    int r0 = blockIdx.x * 64;

    float acc[4][8];
#pragma unroll
    for (int i = 0; i < 4; i++)
#pragma unroll
        for (int j = 0; j < 8; j++) acc[i][j] = 0.f;

    int rowb = (tid >> 4) * 4;      // 0..60
    int colb = (tid & 15) * 8;      // 0..120

    for (int phase = 0; phase < 2; phase++) {
        const float* A = phase ? A1 : A0;
        const float* W = phase ? W1 : W0;
        for (int k0 = 0; k0 < 128; k0 += 8) {
            if (tid < 128) {        // A tile: 64 rows x 8 k, transposed
                int lrow = tid >> 1;
                int lc   = (tid & 1) * 4;
                float4 av = make_float4(0.f, 0.f, 0.f, 0.f);
                int grow = r0 + lrow;
                if (grow < NNODES) av = *(const float4*)&A[grow * FDIM + k0 + lc];
                As[lc + 0][lrow] = av.x;
                As[lc + 1][lrow] = av.y;
                As[lc + 2][lrow] = av.z;
                As[lc + 3][lrow] = av.w;
            }
            {                        // B tile: 8 k x 128 cols, one float4/thread
                int kk = tid >> 5, j4 = (tid & 31) * 4;
                *(float4*)&Bs[kk][j4] = *(const float4*)&W[(k0 + kk) * 128 + j4];
            }
            __syncthreads();
#pragma unroll
            for (int k = 0; k < 8; k++) {
                float a[4], b[8];
                *(float4*)&a[0] = *(const float4*)&As[k][rowb];
                *(float4*)&b[0] = *(const float4*)&Bs[k][colb];
                *(float4*)&b[4] = *(const float4*)&Bs[k][colb + 4];
#pragma unroll
                for (int ii = 0; ii < 4; ii++)
#pragma unroll
                    for (int jj = 0; jj < 8; jj++) acc[ii][jj] += a[ii] * b[jj];
            }
            __syncthreads();
        }
    }
#pragma unroll
    for (int ii = 0; ii < 4; ii++) {
        int grow = r0 + rowb + ii;
        if (grow < NNODES) {
#pragma unroll
            for (int jj = 0; jj < 8; jj += 4) {
                float4 o;
                o.x = fmaxf(acc[ii][jj + 0] + bias[colb + jj + 0], 0.f);
                o.y = fmaxf(acc[ii][jj + 1] + bias[colb + jj + 1], 0.f);
                o.z = fmaxf(acc[ii][jj + 2] + bias[colb + jj + 2], 0.f);
                o.w = fmaxf(acc[ii][jj + 3] + bias[colb + jj + 3], 0.f);
                *(float4*)&Y[(size_t)grow * 128 + colb + jj] = o;
            }
        }
    }
}
#define LAYER_GRID ((NNODES + 63) / 64)

// ================== tf32 mma.sync final GEMM (sm_80+ path) ===================
__device__ __forceinline__ void mma_tf32(float* c, const uint32_t* a, const uint32_t* b) {
    asm volatile(
        "mma.sync.aligned.m16n8k8.row.col.f32.tf32.tf32.f32 "
        "{%0,%1,%2,%3}, {%4,%5,%6,%7}, {%8,%9}, {%0,%1,%2,%3};\n"
        : "+f"(c[0]), "+f"(c[1]), "+f"(c[2]), "+f"(c[3])
        : "r"(a[0]), "r"(a[1]), "r"(a[2]), "r"(a[3]),
          "r"(b[0]), "r"(b[1]));
}

__device__ __forceinline__ void cp16(uint32_t smem_addr, const void* gptr) {
    asm volatile("cp.async.cg.shared.global [%0], [%1], 16;"
                 :: "r"(smem_addr), "l"(gptr));
}

// ---- pre-shuffle A: weights W[k, i] -> fragment blocks ----------------------
__global__ void shufA_kernel(const float* __restrict__ Wl,
                             const float* __restrict__ Wr) {
    const int tile  = blockIdx.x;
    const int chunk = blockIdx.y;
    const int phase = chunk >> 2;
    const int kc    = (chunk & 3) * 32;
    const float* __restrict__ W = phase ? Wr : Wl;
    const int ib   = tile * 128;
    const int warp = threadIdx.x >> 5;
    const int lane = threadIdx.x & 31;
    const int kt   = lane >> 3;
    const int t4v  = lane & 3;
    const int khi  = (lane >> 2) & 1;
    const float* Wp = W + (size_t)(kc + lane) * NNODES + ib;
    uint32_t* dst = g_Ashuf + (size_t)(tile * 8 + chunk) * 4096;
#pragma unroll
    for (int mm = 0; mm < 16; mm++) {
        const int m = warp * 16 + mm;
        float v = 0.f;
        if (ib + m < NNODES) v = Wp[m];
        const int g  = m & 7;
        const int hi = (m >> 3) & 1;
        const int lw = ((g << 2) | t4v) ^ (kt << 3);
        const int r  = (khi << 1) | hi;
        dst[((kt * 8 + warp) * 32 + lw) * 4 + r] = f2tf32(v);
    }
}

// ---- final GEMM: 4 warps, warp tile 64x64, cp.async double-buffered (R12) ----
extern __shared__ uint32_t dynsmem[];   // [2][4096] A + [2][4096] B = 64KB

__global__ void __launch_bounds__(128, 2)
final_tc_kernel(const float* __restrict__ bias,  // [NNODES]
                float* __restrict__ OUT) {       // [NNODES, NNODES]
    uint32_t* sA = dynsmem;
    uint32_t* sB = dynsmem + 8192;

    const int tid  = threadIdx.x;
    const int lane = tid & 31;
    const int warp = tid >> 5;
    const int wm   = warp >> 1;
    const int wn   = warp & 1;
    const int ib   = blockIdx.y * 128;
    const int jb   = blockIdx.x * 128;

    const uint32_t* __restrict__ srcA = g_Ashuf + (size_t)blockIdx.y * 8 * 4096;
    const uint32_t* __restrict__ srcB = g_Bshuf + (size_t)blockIdx.x * 8 * 4096;

    float acc[4][8][4];
#pragma unroll
    for (int mi = 0; mi < 4; mi++)
#pragma unroll
        for (int ni = 0; ni < 8; ni++)
#pragma unroll
            for (int r = 0; r < 4; r++) acc[mi][ni][r] = 0.f;

    const uint32_t sA_u = (uint32_t)__cvta_generic_to_shared(sA);
    const uint32_t sB_u = (uint32_t)__cvta_generic_to_shared(sB);

    auto issue = [&](int chunk) {
        const int buf = chunk & 1;
        const uint32_t* a = srcA + chunk * 4096;
        const uint32_t* b = srcB + chunk * 4096;
        const uint32_t sa = sA_u + buf * 4096 * 4;
        const uint32_t sb = sB_u + buf * 4096 * 4;
#pragma unroll
        for (int it = 0; it < 8; it++) {
            const int off = (tid + it * 128) * 4;
            cp16(sa + off * 4, a + off);
            cp16(sb + off * 4, b + off);
        }
        asm volatile("cp.async.commit_group;");
    };

    issue(0);
    for (int c = 0; c < 8; c++) {
        if (c < 7) {
            issue(c + 1);
            asm volatile("cp.async.wait_group 1;");
        } else {
            asm volatile("cp.async.wait_group 0;");
        }
        __syncthreads();

        const uint32_t* cA = sA + (c & 1) * 4096;
        const uint32_t* cB = sB + (c & 1) * 4096;
#pragma unroll
        for (int kt = 0; kt < 4; kt++) {
            const int lx = lane ^ (kt << 3);
            uint32_t af[4][4];
#pragma unroll
            for (int mi = 0; mi < 4; mi++) {
                const uint4 v = *(const uint4*)&cA[((kt * 8 + wm * 4 + mi) * 32 + lx) * 4];
                af[mi][0] = v.x; af[mi][1] = v.y; af[mi][2] = v.z; af[mi][3] = v.w;
            }
            uint32_t bf[8][2];
#pragma unroll
            for (int ni = 0; ni < 8; ni++) {
                const uint2 v = *(const uint2*)&cB[((kt * 16 + wn * 8 + ni) * 32 + lx) * 2];
                bf[ni][0] = v.x; bf[ni][1] = v.y;
            }
#pragma unroll
            for (int mi = 0; mi < 4; mi++)
#pragma unroll
                for (int ni = 0; ni < 8; ni++)
                    mma_tf32(acc[mi][ni], af[mi], bf[ni]);
        }
        __syncthreads();
    }

    const int g  = lane >> 2;
    const int t4 = lane & 3;
#pragma unroll
    for (int mi = 0; mi < 4; mi++) {
        const int i0 = ib + (wm * 4 + mi) * 16 + g;
        const int i1 = i0 + 8;
        const float bv0 = (i0 < NNODES) ? bias[i0] : 0.f;
        const float bv1 = (i1 < NNODES) ? bias[i1] : 0.f;
#pragma unroll
        for (int ni = 0; ni < 8; ni++) {
            const int j = jb + (wn * 8 + ni) * 8 + t4 * 2;
            if (j < NNODES) {
                if (i0 < NNODES) {
                    float2 o;
                    o.x = fmaxf(acc[mi][ni][0] + bv0, 0.f);
                    o.y = fmaxf(acc[mi][ni][1] + bv0, 0.f);
                    *(float2*)&OUT[(size_t)i0 * NNODES + j] = o;
                }
                if (i1 < NNODES) {
                    float2 o;
                    o.x = fmaxf(acc[mi][ni][2] + bv1, 0.f);
                    o.y = fmaxf(acc[mi][ni][3] + bv1, 0.f);
                    *(float2*)&OUT[(size_t)i1 * NNODES + j] = o;
                }
            }
        }
    }
}

// ---------------- launch ------------------------------------------------------
extern "C" void kernel_launch(void* const* d_in, const int* in_sizes, int n_in,
                              void* d_out, int out_size) {
    const float* x   = (const float*)d_in[0];
    const int*   ei  = (const int*)d_in[1];
    const int*   src = ei;
    const int*   dst = ei + NEDGES;
    const float *Wl_e1 = (const float*)d_in[2],  *bl_e1 = (const float*)d_in[3],  *Wr_e1 = (const float*)d_in[4];
    const float *Wl_e2 = (const float*)d_in[5],  *bl_e2 = (const float*)d_in[6],  *Wr_e2 = (const float*)d_in[7];
    const float *Wl_a1 = (const float*)d_in[8],  *bl_a1 = (const float*)d_in[9],  *Wr_a1 = (const float*)d_in[10];
    const float *Wl_a2 = (const float*)d_in[11], *bl_a2 = (const float*)d_in[12], *Wr_a2 = (const float*)d_in[13];
    const float *Wl_s1 = (const float*)d_in[14], *bl_s1 = (const float*)d_in[15], *Wr_s1 = (const float*)d_in[16];
    const float *Wl_s2 = (const float*)d_in[17], *bl_s2 = (const float*)d_in[18], *Wr_s2 = (const float*)d_in[19];

    float* out    = (float*)d_out;
    float* xh_out = out + (size_t)NNODES * NNODES;

    float *pB1, *pB2, *pB3, *pAGG, *pAGG2;
    cudaGetSymbolAddress((void**)&pB1,   g_B1);
    cudaGetSymbolAddress((void**)&pB2,   g_B2);
    cudaGetSymbolAddress((void**)&pB3,   g_B3);
    cudaGetSymbolAddress((void**)&pAGG,  g_AGG);
    cudaGetSymbolAddress((void**)&pAGG2, g_AGG2);

    static cudaStream_t s_a = nullptr;
    static cudaEvent_t ev0 = nullptr, ev_shufA = nullptr, ev_fork = nullptr, ev_join = nullptr;
    if (!s_a) {
        cudaStreamCreateWithFlags(&s_a, cudaStreamNonBlocking);
        cudaEventCreateWithFlags(&ev0,      cudaEventDisableTiming);
        cudaEventCreateWithFlags(&ev_shufA, cudaEventDisableTiming);
        cudaEventCreateWithFlags(&ev_fork,  cudaEventDisableTiming);
        cudaEventCreateWithFlags(&ev_join,  cudaEventDisableTiming);
        cudaFuncSetAttribute(final_tc_kernel,
                             cudaFuncAttributeMaxDynamicSharedMemorySize, 65536);
    }

    dim3 fg((NNODES + 127) / 128, (NNODES + 127) / 128);  // 79x79
    dim3 sgA(NTILES, 8);

    // fork side stream at t=0: shufA runs concurrently with CSR build
    cudaEventRecord(ev0, 0);
    cudaStreamWaitEvent(s_a, ev0, 0);
    shufA_kernel<<<sgA, 256, 0, s_a>>>(Wl_s2, Wr_s2);
    cudaEventRecord(ev_shufA, s_a);

    // CSR build (main)
    zero_kernel<<<(NNODES + 255) / 256, 256>>>();
    count_kernel<<<(NEDGES + 255) / 256, 256>>>(dst);
    scan_kernel<<<1, 1024>>>();
    fill_kernel<<<(NEDGES + 255) / 256, 256>>>(src, dst);

    // encoder (shared prefix)
    agg_kernel<<<AGG_GRID, 256>>>(x, pAGG);
    layer_kernel<<<LAYER_GRID, 256>>>(pAGG, x, Wl_e1, Wr_e1, bl_e1, pB1);       // h1
    agg_kernel<<<AGG_GRID, 256>>>(pB1, pAGG);
    layer_kernel<<<LAYER_GRID, 256>>>(pAGG, pB1, Wl_e2, Wr_e2, bl_e2, pB2);     // h2

    // fork: attribute decoder on side stream
    cudaEventRecord(ev_fork, 0);
    cudaStreamWaitEvent(s_a, ev_fork, 0);
    agg_kernel<<<AGG_GRID, 256, 0, s_a>>>(pB2, pAGG2);
    layer_kernel<<<LAYER_GRID, 256, 0, s_a>>>(pAGG2, pB2, Wl_a1, Wr_a1, bl_a1, pB3);   // a1
    agg_kernel<<<AGG_GRID, 256, 0, s_a>>>(pB3, pAGG2);
    layer_kernel<<<LAYER_GRID, 256, 0, s_a>>>(pAGG2, pB3, Wl_a2, Wr_a2, bl_a2, xh_out);// xh
    cudaEventRecord(ev_join, s_a);

    // structure decoder + final GEMM on main stream
    agg_kernel<<<AGG_GRID, 256>>>(pB2, pAGG);
    layer_kernel<<<LAYER_GRID, 256>>>(pAGG, pB2, Wl_s1, Wr_s1, bl_s1, pB1);     // s1
    agg_shuf_kernel<<<AGG_GRID, 256>>>(pB1);      // B chunks 0-7 (agg + own-row merged)
    cudaStreamWaitEvent(0, ev_shufA, 0);
    final_tc_kernel<<<fg, 128, 65536>>>(bl_s2, out);                    // s

    cudaStreamWaitEvent(0, ev_join, 0);
}

// round 17
// speedup vs baseline: 1.0802x; 1.0557x over previous
#include <cuda_runtime.h>
#include <cstdint>
#include <cstddef>

#define NNODES 10000
#define NEDGES 320000
#define FDIM   128
#define NTILES 79            // ceil(10000/128)

// ---------------- device scratch (allocation-free rule: __device__ globals) ---
__device__ float g_B1[NNODES * FDIM];   // h1 / s1out
__device__ float g_B2[NNODES * FDIM];   // h2
__device__ float g_B3[NNODES * FDIM];   // a1out (a-branch private)
__device__ float g_AGG[NNODES * FDIM];  // s-branch agg buffer
__device__ float g_AGG2[NNODES * FDIM]; // a-branch agg buffer
__device__ float g_R[NNODES * FDIM];    // root-GEMM buffer (serially reused)
__device__ float g_inv[NNODES];
__device__ int   g_deg[NNODES];
__device__ int   g_cur[NNODES];
__device__ int   g_ptr[NNODES + 1];
__device__ int   g_csrc[NEDGES];
// pre-shuffled tf32 operands for the final GEMM: [tile][chunk][4096] u32
__device__ uint32_t g_Ashuf[NTILES * 8 * 4096];   // ~10.3 MB
__device__ uint32_t g_Bshuf[NTILES * 8 * 4096];   // ~10.3 MB

// ---------------- CSR construction -------------------------------------------
__global__ void zero_kernel() {
    int i = blockIdx.x * blockDim.x + threadIdx.x;
    if (i < NNODES) { g_deg[i] = 0; g_cur[i] = 0; }
}

__global__ void count_kernel(const int* __restrict__ dst) {
    int e = blockIdx.x * blockDim.x + threadIdx.x;
    if (e < NEDGES) atomicAdd(&g_deg[dst[e]], 1);
}

__global__ void __launch_bounds__(1024) scan_kernel() {
    __shared__ int wtot[32];
    const int tid  = threadIdx.x;
    const int lane = tid & 31, wid = tid >> 5;
    const int base = tid * 10;
    int v[10], loc[10];
    int tot = 0;
#pragma unroll
    for (int i = 0; i < 10; i++) {
        v[i] = (base + i < NNODES) ? g_deg[base + i] : 0;
        loc[i] = tot;
        tot += v[i];
    }
    int inc = tot;
#pragma unroll
    for (int off = 1; off < 32; off <<= 1) {
        int t = __shfl_up_sync(0xffffffffu, inc, off);
        if (lane >= off) inc += t;
    }
    if (lane == 31) wtot[wid] = inc;
    __syncthreads();
    if (wid == 0) {
        int w = wtot[lane];
#pragma unroll
        for (int off = 1; off < 32; off <<= 1) {
            int t = __shfl_up_sync(0xffffffffu, w, off);
            if (lane >= off) w += t;
        }
        wtot[lane] = w;
    }
    __syncthreads();
    const int offset = inc - tot + (wid > 0 ? wtot[wid - 1] : 0);  // exclusive
#pragma unroll
    for (int i = 0; i < 10; i++) {
        const int idx = base + i;
        if (idx < NNODES) {
            g_ptr[idx] = offset + loc[i];
            g_inv[idx] = 1.0f / fmaxf((float)v[i], 1.0f);
        }
    }
    if (tid == 1023) g_ptr[NNODES] = offset + tot;
}

__global__ void fill_kernel(const int* __restrict__ src, const int* __restrict__ dst) {
    int e = blockIdx.x * blockDim.x + threadIdx.x;
    if (e < NEDGES) {
        int d = dst[e];
        int pos = g_ptr[d] + atomicAdd(&g_cur[d], 1);
        g_csrc[pos] = src[e];
    }
}

// ---------------- mean aggregation: one WARP per node (R12) -------------------
__global__ void agg_kernel(const float* __restrict__ X, float* __restrict__ O) {
    const int gw   = (blockIdx.x * blockDim.x + threadIdx.x) >> 5;  // node
    const int lane = threadIdx.x & 31;
    if (gw >= NNODES) return;
    const float4* __restrict__ Xv = (const float4*)X;
    const int beg = g_ptr[gw], end = g_ptr[gw + 1];
    float4 a0 = make_float4(0.f, 0.f, 0.f, 0.f);
    float4 a1 = make_float4(0.f, 0.f, 0.f, 0.f);
    float4 a2 = make_float4(0.f, 0.f, 0.f, 0.f);
    float4 a3 = make_float4(0.f, 0.f, 0.f, 0.f);
    int e = beg;
    for (; e + 4 <= end; e += 4) {
        const int i0 = g_csrc[e], i1 = g_csrc[e + 1];
        const int i2 = g_csrc[e + 2], i3 = g_csrc[e + 3];
        const float4 v0 = Xv[i0 * 32 + lane];
        const float4 v1 = Xv[i1 * 32 + lane];
        const float4 v2 = Xv[i2 * 32 + lane];
        const float4 v3 = Xv[i3 * 32 + lane];
        a0.x += v0.x; a0.y += v0.y; a0.z += v0.z; a0.w += v0.w;
        a1.x += v1.x; a1.y += v1.y; a1.z += v1.z; a1.w += v1.w;
        a2.x += v2.x; a2.y += v2.y; a2.z += v2.z; a2.w += v2.w;
        a3.x += v3.x; a3.y += v3.y; a3.z += v3.z; a3.w += v3.w;
    }
    for (; e < end; e++) {
        const float4 v = Xv[g_csrc[e] * 32 + lane];
        a0.x += v.x; a0.y += v.y; a0.z += v.z; a0.w += v.w;
    }
    const float inv = g_inv[gw];
    float4 o;
    o.x = (a0.x + a1.x + a2.x + a3.x) * inv;
    o.y = (a0.y + a1.y + a2.y + a3.y) * inv;
    o.z = (a0.z + a1.z + a2.z + a3.z) * inv;
    o.w = (a0.w + a1.w + a2.w + a3.w) * inv;
    ((float4*)O)[gw * 32 + lane] = o;
}
#define AGG_GRID ((NNODES * 32 + 255) / 256)

__device__ __forceinline__ uint32_t f2tf32(float v) {
    uint32_t t;
    asm("cvt.rna.tf32.f32 %0, %1;" : "=r"(t) : "f"(v));
    return t;
}

// ---- fused: final aggregation -> shuffled B chunks 0-3, own-row -> 4-7 -------
__global__ void agg_shuf_kernel(const float* __restrict__ X) {  // X = S1
    const int gw   = (blockIdx.x * blockDim.x + threadIdx.x) >> 5;  // node j
    const int lane = threadIdx.x & 31;
    if (gw >= NNODES) return;
    const float4* __restrict__ Xv = (const float4*)X;
    const int beg = g_ptr[gw], end = g_ptr[gw + 1];
    float4 a0 = make_float4(0.f, 0.f, 0.f, 0.f);
    float4 a1 = make_float4(0.f, 0.f, 0.f, 0.f);
    float4 a2 = make_float4(0.f, 0.f, 0.f, 0.f);
    float4 a3 = make_float4(0.f, 0.f, 0.f, 0.f);
    int e = beg;
    for (; e + 4 <= end; e += 4) {
        const int i0 = g_csrc[e], i1 = g_csrc[e + 1];
        const int i2 = g_csrc[e + 2], i3 = g_csrc[e + 3];
        const float4 v0 = Xv[i0 * 32 + lane];
        const float4 v1 = Xv[i1 * 32 + lane];
        const float4 v2 = Xv[i2 * 32 + lane];
        const float4 v3 = Xv[i3 * 32 + lane];
        a0.x += v0.x; a0.y += v0.y; a0.z += v0.z; a0.w += v0.w;
        a1.x += v1.x; a1.y += v1.y; a1.z += v1.z; a1.w += v1.w;
        a2.x += v2.x; a2.y += v2.y; a2.z += v2.z; a2.w += v2.w;
        a3.x += v3.x; a3.y += v3.y; a3.z += v3.z; a3.w += v3.w;
    }
    for (; e < end; e++) {
        const float4 v = Xv[g_csrc[e] * 32 + lane];
        a0.x += v.x; a0.y += v.y; a0.z += v.z; a0.w += v.w;
    }
    const float inv = g_inv[gw];
    float ov[4];
    ov[0] = (a0.x + a1.x + a2.x + a3.x) * inv;
    ov[1] = (a0.y + a1.y + a2.y + a3.y) * inv;
    ov[2] = (a0.z + a1.z + a2.z + a3.z) * inv;
    ov[3] = (a0.w + a1.w + a2.w + a3.w) * inv;

    const float4 own = Xv[gw * 32 + lane];
    float sv[4] = {own.x, own.y, own.z, own.w};

    const int tile  = gw >> 7;
    const int jloc  = gw & 127;
    const int nt    = jloc >> 3;
    const int g     = jloc & 7;
    const int chunk = lane >> 3;
    uint32_t* dst0 = g_Bshuf + (size_t)(tile * 8 + chunk) * 4096;      // AGG phase
    uint32_t* dst1 = g_Bshuf + (size_t)(tile * 8 + 4 + chunk) * 4096;  // S1 phase
#pragma unroll
    for (int e2 = 0; e2 < 4; e2++) {
        const int k   = 4 * lane + e2;
        const int kl2 = k & 31;
        const int kt  = kl2 >> 3;
        const int kl  = kl2 & 7;
        const int lw  = ((g << 2) | (kl & 3)) ^ (kt << 3);
        const int r   = kl >> 2;
        const int slot = ((kt * 16 + nt) * 32 + lw) * 2 + r;
        dst0[slot] = f2tf32(ov[e2]);
        dst1[slot] = f2tf32(sv[e2]);
    }
}

// ---------------- full SAGE layer (2-phase, for the a-branch) ----------------
__global__ void __launch_bounds__(256)
layer_kernel(const float* __restrict__ A0,
             const float* __restrict__ A1,
             const float* __restrict__ W0,
             const float* __restrict__ W1,
             const float* __restrict__ bias,
             float* __restrict__ Y) {
    __shared__ float As[8][64];
    __shared__ float Bs[8][128];
    int tid = threadIdx.x;
    int r0 = blockIdx.x * 64;

    float acc[4][8];
#pragma unroll
    for (int i = 0; i < 4; i++)
#pragma unroll
        for (int j = 0; j < 8; j++) acc[i][j] = 0.f;

    int rowb = (tid >> 4) * 4;
    int colb = (tid & 15) * 8;

    for (int phase = 0; phase < 2; phase++) {
        const float* A = phase ? A1 : A0;
        const float* W = phase ? W1 : W0;
        for (int k0 = 0; k0 < 128; k0 += 8) {
            if (tid < 128) {
                int lrow = tid >> 1;
                int lc   = (tid & 1) * 4;
                float4 av = make_float4(0.f, 0.f, 0.f, 0.f);
                int grow = r0 + lrow;
                if (grow < NNODES) av = *(const float4*)&A[grow * FDIM + k0 + lc];
                As[lc + 0][lrow] = av.x;
                As[lc + 1][lrow] = av.y;
                As[lc + 2][lrow] = av.z;
                As[lc + 3][lrow] = av.w;
            }
            {
                int kk = tid >> 5, j4 = (tid & 31) * 4;
                *(float4*)&Bs[kk][j4] = *(const float4*)&W[(k0 + kk) * 128 + j4];
            }
            __syncthreads();
#pragma unroll
            for (int k = 0; k < 8; k++) {
                float a[4], b[8];
                *(float4*)&a[0] = *(const float4*)&As[k][rowb];
                *(float4*)&b[0] = *(const float4*)&Bs[k][colb];
                *(float4*)&b[4] = *(const float4*)&Bs[k][colb + 4];
#pragma unroll
                for (int ii = 0; ii < 4; ii++)
#pragma unroll
                    for (int jj = 0; jj < 8; jj++) acc[ii][jj] += a[ii] * b[jj];
            }
            __syncthreads();
        }
    }
#pragma unroll
    for (int ii = 0; ii < 4; ii++) {
        int grow = r0 + rowb + ii;
        if (grow < NNODES) {
#pragma unroll
            for (int jj = 0; jj < 8; jj += 4) {
                float4 o;
                o.x = fmaxf(acc[ii][jj + 0] + bias[colb + jj + 0], 0.f);
                o.y = fmaxf(acc[ii][jj + 1] + bias[colb + jj + 1], 0.f);
                o.z = fmaxf(acc[ii][jj + 2] + bias[colb + jj + 2], 0.f);
                o.w = fmaxf(acc[ii][jj + 3] + bias[colb + jj + 3], 0.f);
                *(float4*)&Y[(size_t)grow * 128 + colb + jj] = o;
            }
        }
    }
}
#define LAYER_GRID ((NNODES + 63) / 64)

// ---------------- root GEMM: R = X@W + b (no relu), single phase --------------
__global__ void __launch_bounds__(256)
rootmm_kernel(const float* __restrict__ X,
              const float* __restrict__ W,
              const float* __restrict__ bias,
              float* __restrict__ Y) {
    __shared__ float As[8][64];
    __shared__ float Bs[8][128];
    int tid = threadIdx.x;
    int r0 = blockIdx.x * 64;

    float acc[4][8];
#pragma unroll
    for (int i = 0; i < 4; i++)
#pragma unroll
        for (int j = 0; j < 8; j++) acc[i][j] = 0.f;

    int rowb = (tid >> 4) * 4;
    int colb = (tid & 15) * 8;

    for (int k0 = 0; k0 < 128; k0 += 8) {
        if (tid < 128) {
            int lrow = tid >> 1;
            int lc   = (tid & 1) * 4;
            float4 av = make_float4(0.f, 0.f, 0.f, 0.f);
            int grow = r0 + lrow;
            if (grow < NNODES) av = *(const float4*)&X[grow * FDIM + k0 + lc];
            As[lc + 0][lrow] = av.x;
            As[lc + 1][lrow] = av.y;
            As[lc + 2][lrow] = av.z;
            As[lc + 3][lrow] = av.w;
        }
        {
            int kk = tid >> 5, j4 = (tid & 31) * 4;
            *(float4*)&Bs[kk][j4] = *(const float4*)&W[(k0 + kk) * 128 + j4];
        }
        __syncthreads();
#pragma unroll
        for (int k = 0; k < 8; k++) {
            float a[4], b[8];
            *(float4*)&a[0] = *(const float4*)&As[k][rowb];
            *(float4*)&b[0] = *(const float4*)&Bs[k][colb];
            *(float4*)&b[4] = *(const float4*)&Bs[k][colb + 4];
#pragma unroll
            for (int ii = 0; ii < 4; ii++)
#pragma unroll
                for (int jj = 0; jj < 8; jj++) acc[ii][jj] += a[ii] * b[jj];
        }
        __syncthreads();
    }
#pragma unroll
    for (int ii = 0; ii < 4; ii++) {
        int grow = r0 + rowb + ii;
        if (grow < NNODES) {
#pragma unroll
            for (int jj = 0; jj < 8; jj += 4) {
                float4 o;
                o.x = acc[ii][jj + 0] + bias[colb + jj + 0];
                o.y = acc[ii][jj + 1] + bias[colb + jj + 1];
                o.z = acc[ii][jj + 2] + bias[colb + jj + 2];
                o.w = acc[ii][jj + 3] + bias[colb + jj + 3];
                *(float4*)&Y[(size_t)grow * 128 + colb + jj] = o;
            }
        }
    }
}

// ---------------- lite layer: Y = relu(AGG@Wl + R), single phase --------------
__global__ void __launch_bounds__(256)
layer_lite_kernel(const float* __restrict__ A,   // AGG
                  const float* __restrict__ W,   // Wl
                  const float* __restrict__ P,   // precomputed root term [N,128]
                  float* __restrict__ Y) {
    __shared__ float As[8][64];
    __shared__ float Bs[8][128];
    int tid = threadIdx.x;
    int r0 = blockIdx.x * 64;

    float acc[4][8];
#pragma unroll
    for (int i = 0; i < 4; i++)
#pragma unroll
        for (int j = 0; j < 8; j++) acc[i][j] = 0.f;

    int rowb = (tid >> 4) * 4;
    int colb = (tid & 15) * 8;

    for (int k0 = 0; k0 < 128; k0 += 8) {
        if (tid < 128) {
            int lrow = tid >> 1;
            int lc   = (tid & 1) * 4;
            float4 av = make_float4(0.f, 0.f, 0.f, 0.f);
            int grow = r0 + lrow;
            if (grow < NNODES) av = *(const float4*)&A[grow * FDIM + k0 + lc];
            As[lc + 0][lrow] = av.x;
            As[lc + 1][lrow] = av.y;
            As[lc + 2][lrow] = av.z;
            As[lc + 3][lrow] = av.w;
        }
        {
            int kk = tid >> 5, j4 = (tid & 31) * 4;
            *(float4*)&Bs[kk][j4] = *(const float4*)&W[(k0 + kk) * 128 + j4];
        }
        __syncthreads();
#pragma unroll
        for (int k = 0; k < 8; k++) {
            float a[4], b[8];
            *(float4*)&a[0] = *(const float4*)&As[k][rowb];
            *(float4*)&b[0] = *(const float4*)&Bs[k][colb];
            *(float4*)&b[4] = *(const float4*)&Bs[k][colb + 4];
#pragma unroll
            for (int ii = 0; ii < 4; ii++)
#pragma unroll
                for (int jj = 0; jj < 8; jj++) acc[ii][jj] += a[ii] * b[jj];
        }
        __syncthreads();
    }
#pragma unroll
    for (int ii = 0; ii < 4; ii++) {
        int grow = r0 + rowb + ii;
        if (grow < NNODES) {
#pragma unroll
            for (int jj = 0; jj < 8; jj += 4) {
                const float4 p = *(const float4*)&P[(size_t)grow * 128 + colb + jj];
                float4 o;
                o.x = fmaxf(acc[ii][jj + 0] + p.x, 0.f);
                o.y = fmaxf(acc[ii][jj + 1] + p.y, 0.f);
                o.z = fmaxf(acc[ii][jj + 2] + p.z, 0.f);
                o.w = fmaxf(acc[ii][jj + 3] + p.w, 0.f);
                *(float4*)&Y[(size_t)grow * 128 + colb + jj] = o;
            }
        }
    }
}

// ================== tf32 mma.sync final GEMM (R12-proven) ====================
__device__ __forceinline__ void mma_tf32(float* c, const uint32_t* a, const uint32_t* b) {
    asm volatile(
        "mma.sync.aligned.m16n8k8.row.col.f32.tf32.tf32.f32 "
        "{%0,%1,%2,%3}, {%4,%5,%6,%7}, {%8,%9}, {%0,%1,%2,%3};\n"
        : "+f"(c[0]), "+f"(c[1]), "+f"(c[2]), "+f"(c[3])
        : "r"(a[0]), "r"(a[1]), "r"(a[2]), "r"(a[3]),
          "r"(b[0]), "r"(b[1]));
}

__device__ __forceinline__ void cp16(uint32_t smem_addr, const void* gptr) {
    asm volatile("cp.async.cg.shared.global [%0], [%1], 16;"
                 :: "r"(smem_addr), "l"(gptr));
}

// ---- pre-shuffle A: weights W[k, i] -> fragment blocks ----------------------
__global__ void shufA_kernel(const float* __restrict__ Wl,
                             const float* __restrict__ Wr) {
    const int tile  = blockIdx.x;
    const int chunk = blockIdx.y;
    const int phase = chunk >> 2;
    const int kc    = (chunk & 3) * 32;
    const float* __restrict__ W = phase ? Wr : Wl;
    const int ib   = tile * 128;
    const int warp = threadIdx.x >> 5;
    const int lane = threadIdx.x & 31;
    const int kt   = lane >> 3;
    const int t4v  = lane & 3;
    const int khi  = (lane >> 2) & 1;
    const float* Wp = W + (size_t)(kc + lane) * NNODES + ib;
    uint32_t* dst = g_Ashuf + (size_t)(tile * 8 + chunk) * 4096;
#pragma unroll
    for (int mm = 0; mm < 16; mm++) {
        const int m = warp * 16 + mm;
        float v = 0.f;
        if (ib + m < NNODES) v = Wp[m];
        const int g  = m & 7;
        const int hi = (m >> 3) & 1;
        const int lw = ((g << 2) | t4v) ^ (kt << 3);
        const int r  = (khi << 1) | hi;
        dst[((kt * 8 + warp) * 32 + lw) * 4 + r] = f2tf32(v);
    }
}

// ---- final GEMM: 4 warps, warp tile 64x64, cp.async double-buffered ----------
extern __shared__ uint32_t dynsmem[];   // [2][4096] A + [2][4096] B = 64KB

__global__ void __launch_bounds__(128, 2)
final_tc_kernel(const float* __restrict__ bias,  // [NNODES]
                float* __restrict__ OUT) {       // [NNODES, NNODES]
    uint32_t* sA = dynsmem;
    uint32_t* sB = dynsmem + 8192;

    const int tid  = threadIdx.x;
    const int lane = tid & 31;
    const int warp = tid >> 5;
    const int wm   = warp >> 1;
    const int wn   = warp & 1;
    const int ib   = blockIdx.y * 128;
    const int jb   = blockIdx.x * 128;

    const uint32_t* __restrict__ srcA = g_Ashuf + (size_t)blockIdx.y * 8 * 4096;
    const uint32_t* __restrict__ srcB = g_Bshuf + (size_t)blockIdx.x * 8 * 4096;

    float acc[4][8][4];
#pragma unroll
    for (int mi = 0; mi < 4; mi++)
#pragma unroll
        for (int ni = 0; ni < 8; ni++)
#pragma unroll
            for (int r = 0; r < 4; r++) acc[mi][ni][r] = 0.f;

    const uint32_t sA_u = (uint32_t)__cvta_generic_to_shared(sA);
    const uint32_t sB_u = (uint32_t)__cvta_generic_to_shared(sB);

    auto issue = [&](int chunk) {
        const int buf = chunk & 1;
        const uint32_t* a = srcA + chunk * 4096;
        const uint32_t* b = srcB + chunk * 4096;
        const uint32_t sa = sA_u + buf * 4096 * 4;
        const uint32_t sb = sB_u + buf * 4096 * 4;
#pragma unroll
        for (int it = 0; it < 8; it++) {
            const int off = (tid + it * 128) * 4;
            cp16(sa + off * 4, a + off);
            cp16(sb + off * 4, b + off);
        }
        asm volatile("cp.async.commit_group;");
    };

    issue(0);
    for (int c = 0; c < 8; c++) {
        if (c < 7) {
            issue(c + 1);
            asm volatile("cp.async.wait_group 1;");
        } else {
            asm volatile("cp.async.wait_group 0;");
        }
        __syncthreads();

        const uint32_t* cA = sA + (c & 1) * 4096;
        const uint32_t* cB = sB + (c & 1) * 4096;
#pragma unroll
        for (int kt = 0; kt < 4; kt++) {
            const int lx = lane ^ (kt << 3);
            uint32_t af[4][4];
#pragma unroll
            for (int mi = 0; mi < 4; mi++) {
                const uint4 v = *(const uint4*)&cA[((kt * 8 + wm * 4 + mi) * 32 + lx) * 4];
                af[mi][0] = v.x; af[mi][1] = v.y; af[mi][2] = v.z; af[mi][3] = v.w;
            }
            uint32_t bf[8][2];
#pragma unroll
            for (int ni = 0; ni < 8; ni++) {
                const uint2 v = *(const uint2*)&cB[((kt * 16 + wn * 8 + ni) * 32 + lx) * 2];
                bf[ni][0] = v.x; bf[ni][1] = v.y;
            }
#pragma unroll
            for (int mi = 0; mi < 4; mi++)
#pragma unroll
                for (int ni = 0; ni < 8; ni++)
                    mma_tf32(acc[mi][ni], af[mi], bf[ni]);
        }
        __syncthreads();
    }

    const int g  = lane >> 2;
    const int t4 = lane & 3;
#pragma unroll
    for (int mi = 0; mi < 4; mi++) {
        const int i0 = ib + (wm * 4 + mi) * 16 + g;
        const int i1 = i0 + 8;
        const float bv0 = (i0 < NNODES) ? bias[i0] : 0.f;
        const float bv1 = (i1 < NNODES) ? bias[i1] : 0.f;
#pragma unroll
        for (int ni = 0; ni < 8; ni++) {
            const int j = jb + (wn * 8 + ni) * 8 + t4 * 2;
            if (j < NNODES) {
                if (i0 < NNODES) {
                    float2 o;
                    o.x = fmaxf(acc[mi][ni][0] + bv0, 0.f);
                    o.y = fmaxf(acc[mi][ni][1] + bv0, 0.f);
                    *(float2*)&OUT[(size_t)i0 * NNODES + j] = o;
                }
                if (i1 < NNODES) {
                    float2 o;
                    o.x = fmaxf(acc[mi][ni][2] + bv1, 0.f);
                    o.y = fmaxf(acc[mi][ni][3] + bv1, 0.f);
                    *(float2*)&OUT[(size_t)i1 * NNODES + j] = o;
                }
            }
        }
    }
}

// ---------------- launch ------------------------------------------------------
extern "C" void kernel_launch(void* const* d_in, const int* in_sizes, int n_in,
                              void* d_out, int out_size) {
    const float* x   = (const float*)d_in[0];
    const int*   ei  = (const int*)d_in[1];
    const int*   src = ei;
    const int*   dst = ei + NEDGES;
    const float *Wl_e1 = (const float*)d_in[2],  *bl_e1 = (const float*)d_in[3],  *Wr_e1 = (const float*)d_in[4];
    const float *Wl_e2 = (const float*)d_in[5],  *bl_e2 = (const float*)d_in[6],  *Wr_e2 = (const float*)d_in[7];
    const float *Wl_a1 = (const float*)d_in[8],  *bl_a1 = (const float*)d_in[9],  *Wr_a1 = (const float*)d_in[10];
    const float *Wl_a2 = (const float*)d_in[11], *bl_a2 = (const float*)d_in[12], *Wr_a2 = (const float*)d_in[13];
    const float *Wl_s1 = (const float*)d_in[14], *bl_s1 = (const float*)d_in[15], *Wr_s1 = (const float*)d_in[16];
    const float *Wl_s2 = (const float*)d_in[17], *bl_s2 = (const float*)d_in[18], *Wr_s2 = (const float*)d_in[19];

    float* out    = (float*)d_out;
    float* xh_out = out + (size_t)NNODES * NNODES;

    float *pB1, *pB2, *pB3, *pAGG, *pAGG2, *pR;
    cudaGetSymbolAddress((void**)&pB1,   g_B1);
    cudaGetSymbolAddress((void**)&pB2,   g_B2);
    cudaGetSymbolAddress((void**)&pB3,   g_B3);
    cudaGetSymbolAddress((void**)&pAGG,  g_AGG);
    cudaGetSymbolAddress((void**)&pAGG2, g_AGG2);
    cudaGetSymbolAddress((void**)&pR,    g_R);

    static cudaStream_t s_a = nullptr, s_r = nullptr;
    static cudaEvent_t ev0 = nullptr, ev_shufA = nullptr, ev_join = nullptr;
    static cudaEvent_t ev_h1 = nullptr, ev_h2 = nullptr;
    static cudaEvent_t ev_r1 = nullptr, ev_r2 = nullptr, ev_r3 = nullptr;
    if (!s_a) {
        cudaStreamCreateWithFlags(&s_a, cudaStreamNonBlocking);
        cudaStreamCreateWithFlags(&s_r, cudaStreamNonBlocking);
        cudaEventCreateWithFlags(&ev0,      cudaEventDisableTiming);
        cudaEventCreateWithFlags(&ev_shufA, cudaEventDisableTiming);
        cudaEventCreateWithFlags(&ev_join,  cudaEventDisableTiming);
        cudaEventCreateWithFlags(&ev_h1,    cudaEventDisableTiming);
        cudaEventCreateWithFlags(&ev_h2,    cudaEventDisableTiming);
        cudaEventCreateWithFlags(&ev_r1,    cudaEventDisableTiming);
        cudaEventCreateWithFlags(&ev_r2,    cudaEventDisableTiming);
        cudaEventCreateWithFlags(&ev_r3,    cudaEventDisableTiming);
        cudaFuncSetAttribute(final_tc_kernel,
                             cudaFuncAttributeMaxDynamicSharedMemorySize, 65536);
    }

    dim3 fg((NNODES + 127) / 128, (NNODES + 127) / 128);  // 79x79
    dim3 sgA(NTILES, 8);

    // t=0 forks
    cudaEventRecord(ev0, 0);
    cudaStreamWaitEvent(s_a, ev0, 0);
    cudaStreamWaitEvent(s_r, ev0, 0);

    // side stream a: shufA (final-GEMM weights)
    shufA_kernel<<<sgA, 256, 0, s_a>>>(Wl_s2, Wr_s2);
    cudaEventRecord(ev_shufA, s_a);

    // root stream: R1 = x@Wr_e1 + b  (no CSR dependency, hides under CSR build)
    rootmm_kernel<<<LAYER_GRID, 256, 0, s_r>>>(x, Wr_e1, bl_e1, pR);
    cudaEventRecord(ev_r1, s_r);

    // CSR build (main)
    zero_kernel<<<(NNODES + 255) / 256, 256>>>();
    count_kernel<<<(NEDGES + 255) / 256, 256>>>(dst);
    scan_kernel<<<1, 1024>>>();
    fill_kernel<<<(NEDGES + 255) / 256, 256>>>(src, dst);

    // e1: agg || (R1 already done) -> lite layer
    agg_kernel<<<AGG_GRID, 256>>>(x, pAGG);
    cudaStreamWaitEvent(0, ev_r1, 0);
    layer_lite_kernel<<<LAYER_GRID, 256>>>(pAGG, Wl_e1, pR, pB1);       // h1
    cudaEventRecord(ev_h1, 0);

    // e2: root GEMM on s_r concurrent with agg on main
    cudaStreamWaitEvent(s_r, ev_h1, 0);
    rootmm_kernel<<<LAYER_GRID, 256, 0, s_r>>>(pB1, Wr_e2, bl_e2, pR);
    cudaEventRecord(ev_r2, s_r);
    agg_kernel<<<AGG_GRID, 256>>>(pB1, pAGG);
    cudaStreamWaitEvent(0, ev_r2, 0);
    layer_lite_kernel<<<LAYER_GRID, 256>>>(pAGG, Wl_e2, pR, pB2);       // h2
    cudaEventRecord(ev_h2, 0);

    // a-branch on s_a (off critical path; full 2-phase layers)
    cudaStreamWaitEvent(s_a, ev_h2, 0);
    agg_kernel<<<AGG_GRID, 256, 0, s_a>>>(pB2, pAGG2);
    layer_kernel<<<LAYER_GRID, 256, 0, s_a>>>(pAGG2, pB2, Wl_a1, Wr_a1, bl_a1, pB3);   // a1
    agg_kernel<<<AGG_GRID, 256, 0, s_a>>>(pB3, pAGG2);
    layer_kernel<<<LAYER_GRID, 256, 0, s_a>>>(pAGG2, pB3, Wl_a2, Wr_a2, bl_a2, xh_out);// xh
    cudaEventRecord(ev_join, s_a);

    // s1: root GEMM on s_r concurrent with agg on main
    cudaStreamWaitEvent(s_r, ev_h2, 0);
    rootmm_kernel<<<LAYER_GRID, 256, 0, s_r>>>(pB2, Wr_s1, bl_s1, pR);
    cudaEventRecord(ev_r3, s_r);
    agg_kernel<<<AGG_GRID, 256>>>(pB2, pAGG);
    cudaStreamWaitEvent(0, ev_r3, 0);
    layer_lite_kernel<<<LAYER_GRID, 256>>>(pAGG, Wl_s1, pR, pB1);       // s1
    agg_shuf_kernel<<<AGG_GRID, 256>>>(pB1);      // B chunks 0-7
    cudaStreamWaitEvent(0, ev_shufA, 0);
    final_tc_kernel<<<fg, 128, 65536>>>(bl_s2, out);                    // s

    cudaStreamWaitEvent(0, ev_join, 0);
}